// round 7
// baseline (speedup 1.0000x reference)
#include <cuda_runtime.h>
#include <cuda_bf16.h>

// Problem constants
#define BDIM 2048   // batch rows
#define SDIM 1024   // support vectors
#define FDIM 64     // features

// Tiling
#define BM 64       // rows per block = 32 lane-pairs (r, r+32)
#define BN 64       // support cols per block
#define TN 16       // cols per warp (4 warps x 16 = 64 = BN)
#define NTHREADS 128
#define SSPLIT 16   // grid.y; each block covers 1024/16 = 64 S cols

// Precomputed half-angle trig tables in bf16 (same as R6).
// X pre-PAIRED per 64-row block: rows r = blk*64+q and r+32:
//   g_Xb[f*1024 + blk*32 + q] = { bf16x2(cos_r, cos_{r+32}), bf16x2(sin_r, sin_{r+32}) }
// S pre-SPLATTED: g_Scb[f*1024 + j] = bf16x2(cos_j, cos_j); g_Ssb likewise.
__device__ uint2    g_Xb[FDIM * (BDIM / 2)];   // 512 KB
__device__ unsigned g_Scb[FDIM * SDIM];        // 256 KB
__device__ unsigned g_Ssb[FDIM * SDIM];        // 256 KB

static __device__ __forceinline__ __nv_bfloat162 u2bf2(unsigned u) {
    return *reinterpret_cast<__nv_bfloat162*>(&u);
}

// ---------------------------------------------------------------------------
// Kernel A: precompute bf16 trig tables + initialize out[i] = b[0]
// ---------------------------------------------------------------------------
__global__ void precompute_kernel(const float* __restrict__ X,
                                  const float* __restrict__ S,
                                  const float* __restrict__ b,
                                  float* __restrict__ out) {
    int idx = blockIdx.x * blockDim.x + threadIdx.x;

    const int NX2 = FDIM * (BDIM / 2);   // 65536 X pair entries
    const int NS  = FDIM * SDIM;         // 65536

    if (idx < NX2) {
        int f = idx >> 10;               // / 1024
        int e = idx & 1023;
        int blk = e >> 5;
        int q = e & 31;
        int r0 = blk * 64 + q;
        float v0 = X[r0 * FDIM + f];
        float v1 = X[(r0 + 32) * FDIM + f];
        float s0, c0, s1, c1;
        __sincosf(0.5f * v0, &s0, &c0);
        __sincosf(0.5f * v1, &s1, &c1);
        __nv_bfloat162 cp = __floats2bfloat162_rn(c0, c1);  // (lo=r, hi=r+32)
        __nv_bfloat162 sp = __floats2bfloat162_rn(s0, s1);
        g_Xb[idx] = make_uint2(*reinterpret_cast<unsigned*>(&cp),
                               *reinterpret_cast<unsigned*>(&sp));
    } else if (idx < NX2 + NS) {
        int e = idx - NX2;
        int f = e >> 10;
        int j = e & (SDIM - 1);
        float v = S[j * FDIM + f];
        float s, c;
        __sincosf(0.5f * v, &s, &c);
        __nv_bfloat162 cc = __floats2bfloat162_rn(c, c);
        __nv_bfloat162 ss = __floats2bfloat162_rn(s, s);
        g_Scb[e] = *reinterpret_cast<unsigned*>(&cc);
        g_Ssb[e] = *reinterpret_cast<unsigned*>(&ss);
    }

    if (idx < BDIM) {
        out[idx] = b[0];                 // global atomics accumulate on top
    }
}

// ---------------------------------------------------------------------------
// Kernel B: grid (2048/64, 16) = 512 blocks (SINGLE WAVE at 4 blocks/SM),
//   128 threads (4 warps). Lane owns row pair (rowbase+lane, rowbase+lane+32).
//   Warp w owns cols [w*16, w*16+16): S loads broadcast LDS.128 (8 total/iter).
//   Inner iter: 1 LDS.64 (X) + 8 LDS.128 (S) + 48 bf16x2 ops covering
//   64 rows x 16 cols = 1024 positions -> FMA pipe is the sole binder.
// ---------------------------------------------------------------------------
__global__ __launch_bounds__(NTHREADS, 4)
void qkr_main_kernel(const float* __restrict__ W,
                     float* __restrict__ out) {
    __shared__ __align__(16) uint2    sX[FDIM * 32];     // 16 KB  [f*32 + q]
    __shared__ __align__(16) unsigned sSc[FDIM * BN];    // 16 KB  [f*64 + c]
    __shared__ __align__(16) unsigned sSs[FDIM * BN];    // 16 KB
    __shared__ float rowacc[BM];

    const int tid  = threadIdx.x;
    const int lane = tid & 31;
    const int warp = tid >> 5;          // 0..3
    const int col0 = warp * TN;         // 0,16,32,48 (uint4-aligned)
    const int jbase = blockIdx.y * BN;  // 64 support cols for this block

    // Vectorized fills (uint4). X: 1024 uint4; S: 1024 uint4 per array.
    #pragma unroll
    for (int e4 = tid; e4 < 1024; e4 += NTHREADS) {
        int f = e4 >> 4;
        int k = e4 & 15;
        ((uint4*)sX)[e4] =
            *(const uint4*)&g_Xb[f * (BDIM / 2) + blockIdx.x * 32 + k * 2];
        ((uint4*)sSc)[e4] = *(const uint4*)&g_Scb[f * SDIM + jbase + k * 4];
        ((uint4*)sSs)[e4] = *(const uint4*)&g_Ssb[f * SDIM + jbase + k * 4];
    }
    if (tid < BM) rowacc[tid] = 0.0f;
    __syncthreads();

    // p[c] = bf16x2 running product of cos((x - s_c)/2) over the lane's row pair
    __nv_bfloat162 p[TN];
    const __nv_bfloat162 one2 = __float2bfloat162_rn(1.0f);
    #pragma unroll
    for (int c = 0; c < TN; c++) p[c] = one2;

    #pragma unroll 2
    for (int f = 0; f < FDIM; f++) {
        uint2 xv = sX[f * 32 + lane];                    // lane-unique LDS.64
        __nv_bfloat162 xc = u2bf2(xv.x);
        __nv_bfloat162 xs = u2bf2(xv.y);

        // broadcast LDS.128: 4 splatted cols each, 4 loads per array
        const uint4* scp = (const uint4*)&sSc[f * BN + col0];
        const uint4* ssp = (const uint4*)&sSs[f * BN + col0];
        uint4 c0v = scp[0], c1v = scp[1], c2v = scp[2], c3v = scp[3];
        uint4 s0v = ssp[0], s1v = ssp[1], s2v = ssp[2], s3v = ssp[3];
        unsigned scu[TN] = { c0v.x, c0v.y, c0v.z, c0v.w,
                             c1v.x, c1v.y, c1v.z, c1v.w,
                             c2v.x, c2v.y, c2v.z, c2v.w,
                             c3v.x, c3v.y, c3v.z, c3v.w };
        unsigned ssu[TN] = { s0v.x, s0v.y, s0v.z, s0v.w,
                             s1v.x, s1v.y, s1v.z, s1v.w,
                             s2v.x, s2v.y, s2v.z, s2v.w,
                             s3v.x, s3v.y, s3v.z, s3v.w };

        #pragma unroll
        for (int c = 0; c < TN; c++) {
            __nv_bfloat162 t = __hmul2(xc, u2bf2(scu[c]));   // xc*sc
            t = __hfma2(xs, u2bf2(ssu[c]), t);               // + xs*ss
            p[c] = __hmul2(p[c], t);                         // running product
        }
    }

    // Epilogue in f32: K = (prod cos)^2 ; acc += W[j] * K
    float acc0 = 0.0f, acc1 = 0.0f;
    #pragma unroll
    for (int c = 0; c < TN; c++) {
        float w  = __ldg(&W[jbase + col0 + c]);
        float lo = __low2float(p[c]);
        float hi = __high2float(p[c]);
        acc0 = fmaf(w, lo * lo, acc0);
        acc1 = fmaf(w, hi * hi, acc1);
    }

    // Block-level row reduction (4 warps per row), then 1 global atomic/row.
    atomicAdd(&rowacc[lane],      acc0);
    atomicAdd(&rowacc[lane + 32], acc1);
    __syncthreads();
    if (tid < BM) {
        atomicAdd(&out[blockIdx.x * BM + tid], rowacc[tid]);
    }
}

// ---------------------------------------------------------------------------
extern "C" void kernel_launch(void* const* d_in, const int* in_sizes, int n_in,
                              void* d_out, int out_size) {
    const float* X = (const float*)d_in[0];   // [2048, 64]
    const float* S = (const float*)d_in[1];   // [1024, 64]
    const float* W = (const float*)d_in[2];   // [1, 1024]
    const float* b = (const float*)d_in[3];   // [1]
    float* out = (float*)d_out;               // [2048]

    {
        int total = FDIM * (BDIM / 2) + FDIM * SDIM;   // 131072
        int threads = 256;
        int blocks = (total + threads - 1) / threads;
        precompute_kernel<<<blocks, threads>>>(X, S, b, out);
    }
    {
        dim3 grid(BDIM / BM, SSPLIT);   // (32, 16) = 512 blocks, single wave
        qkr_main_kernel<<<grid, NTHREADS>>>(W, out);
    }
}